// round 9
// baseline (speedup 1.0000x reference)
#include <cuda_runtime.h>
#include <cstdint>

// TitansMemory B=16 L=8192 DK=DV=128 — direct recurrence v4: T=4 super-steps.
// 2048 (b,v) row-chains; 2 rows per warp (16-lane halves, 8 floats/lane).
// Per super-step (4 steps): ONE interleaved butterfly over 15 dots from
// pre-state, scalar 4-step recurrence using per-chunk Gram (G=k.k, H=k.q),
// then a rank-4 closed-form state update. Rescaled chunk frame (R8 math).
// 256 CTAs x 128 thr (vgroup 8 rows), 2 CTAs/SM.

#define CSTEPS 16
#define L_SEQ  8192
#define NCH    (L_SEQ / CSTEPS)
#define DK     128

using ull = unsigned long long;

__device__ __forceinline__ ull pk(float lo, float hi) {
    ull r; asm("mov.b64 %0,{%1,%2};" : "=l"(r) : "f"(lo), "f"(hi)); return r;
}
__device__ __forceinline__ float hadd2(ull p) {
    float lo, hi; asm("mov.b64 {%0,%1},%2;" : "=f"(lo), "=f"(hi) : "l"(p));
    return lo + hi;
}
__device__ __forceinline__ ull mul2(ull a, ull b) {
    ull d; asm("mul.rn.f32x2 %0,%1,%2;" : "=l"(d) : "l"(a), "l"(b)); return d;
}
__device__ __forceinline__ ull fma2(ull a, ull b, ull c) {
    ull d; asm("fma.rn.f32x2 %0,%1,%2,%3;" : "=l"(d) : "l"(a), "l"(b), "l"(c)); return d;
}
__device__ __forceinline__ ull add2(ull a, ull b) {
    ull d; asm("add.rn.f32x2 %0,%1,%2;" : "=l"(d) : "l"(a), "l"(b)); return d;
}
__device__ __forceinline__ unsigned su32(const void* p) {
    return (unsigned)__cvta_generic_to_shared(p);
}
__device__ __forceinline__ void cp16(unsigned s, const void* g) {
    asm volatile("cp.async.cg.shared.global [%0],[%1],16;" :: "r"(s), "l"(g));
}
__device__ __forceinline__ void cp4(unsigned s, const void* g) {
    asm volatile("cp.async.ca.shared.global [%0],[%1],4;" :: "r"(s), "l"(g));
}
__device__ __forceinline__ void cp_commit() {
    asm volatile("cp.async.commit_group;" ::: "memory");
}
__device__ __forceinline__ void cp_wait_all() {
    asm volatile("cp.async.wait_group 0;" ::: "memory");
}

// even/odd float4-chunk permutation: lane g reads slots g,16+g = floats 8g..8g+7
__device__ __forceinline__ int perm(int c) { return (c >> 1) | ((c & 1) << 4); }

__global__ __launch_bounds__(128, 2)
void titans_kernel(const float* __restrict__ Q,
                   const float* __restrict__ K,
                   const float* __restrict__ V,
                   float* __restrict__ Y) {
    static constexpr float cCP[16] = {  // 0.98^i
        1.0f, 0.98f, 0.9604f, 0.941192f, 0.92236816f, 0.9039207968f,
        0.8858423809f, 0.8681255332f, 0.8507630226f, 0.8337477621f,
        0.8170728069f, 0.8007313508f, 0.7847167237f, 0.7690223892f,
        0.7536419414f, 0.7385691035f };
    static constexpr float cCY[16] = {  // 0.98^(i+1)
        0.98f, 0.9604f, 0.941192f, 0.92236816f, 0.9039207968f, 0.8858423809f,
        0.8681255332f, 0.8507630226f, 0.8337477621f, 0.8170728069f,
        0.8007313508f, 0.7847167237f, 0.7690223892f, 0.7536419414f,
        0.7385691035f, 0.7237977214f };
    static constexpr float cS[16] = {   // -0.1*(0.9/0.98)^(i+1)
        -0.09183673469f, -0.08433985839f, -0.07745414463f, -0.07113064017f,
        -0.06532344097f, -0.05999029968f, -0.05509252418f, -0.05059456302f,
        -0.04646378542f, -0.04267021926f, -0.03918632342f, -0.03598663375f,
        -0.03304811221f, -0.03034970510f, -0.02787207213f, -0.02559670445f };
    static constexpr float cA[16] = {   // -0.02/0.98^(i+1)
        -0.02040816327f, -0.02082465640f, -0.02124964939f, -0.02168331570f,
        -0.02212583235f, -0.02257738015f, -0.02303814301f, -0.02350830920f,
        -0.02398807061f, -0.02447762307f, -0.02497716640f, -0.02548690449f,
        -0.02600704540f, -0.02653780143f, -0.02707938921f, -0.02763202981f };
    static constexpr float cB[16] = {   // 0.2/0.9^(i+1)
        0.2222222222f, 0.2469135802f, 0.2743484225f, 0.3048315805f,
        0.3387017561f, 0.3763352846f, 0.4181503162f, 0.4646114624f,
        0.5162349582f, 0.5735943980f, 0.6373271089f, 0.7081412321f,
        0.7868235912f, 0.8742484347f, 0.9713871497f, 1.0793190552f };
    // zW coefficient per step: cA[i] + (sum of cS over later steps in SAME
    // super-step) * cB[i]
    static constexpr float cZW4[16] = {
        -0.07216920f, -0.05751226f, -0.04076420f, -0.02168331570f,
        -0.07824097f, -0.06235117f, -0.04419427f, -0.02350830920f,
        -0.08482284f, -0.06759641f, -0.04791243f, -0.02548690449f,
        -0.09195752f, -0.07328280f, -0.05194376f, -0.02763202981f };
    // P per super-step: sum of cS over its 4 steps
    static constexpr float cP4[4] = {
        -0.32476137788f, -0.23100082785f, -0.16430696185f, -0.11686659389f };
    constexpr float C16F = 0.7237977214f;   // 0.98^16
    constexpr float B16F = 0.1853020189f;   // 0.9^16

    __shared__ float kq[2][2][CSTEPS][DK];  // [buf][k/q][t][slot-swizzled d]
    __shared__ float vT[2][8][20];          // [buf][row][t]
    __shared__ float yb[2][CSTEPS][8];      // [buf][t][row]
    __shared__ float Gm[4][4][4];           // [ss][j][l]: k_j.k_l  (j<l used)
    __shared__ float Hm[4][4][4];           // [ss][j][l]: k_j.q_l  (j<=l used)

    const int tid  = threadIdx.x;
    const int w    = tid >> 5;               // warp 0..3
    const int lane = tid & 31;
    const int g    = lane & 15;
    const int half = lane >> 4;
    const int row  = (w << 1) + half;        // 0..7

    const int b     = blockIdx.x >> 4;
    const int vbase = (blockIdx.x & 15) << 3;

    const size_t base = (size_t)b * L_SEQ * DK;
    const float* gk = K + base;
    const float* gq = Q + base;
    const float* gv = V + base;
    float*       gy = Y + base;

    ull W0 = 0, W1 = 0, W2 = 0, W3 = 0;
    ull M0 = 0, M1 = 0, M2 = 0, M3 = 0;

    // ---- preload chunk 0 ----
    {
        #pragma unroll
        for (int u = 0; u < 4; ++u) {
            int id = u * 128 + tid;
            int t = id >> 5, c = id & 31;
            cp16(su32(&kq[0][0][t][perm(c) * 4]), gk + t * DK + c * 4);
            cp16(su32(&kq[0][1][t][perm(c) * 4]), gq + t * DK + c * 4);
        }
        {
            int i = tid >> 3, j = tid & 7;
            cp4(su32(&vT[0][j][i]), gv + (size_t)i * DK + vbase + j);
        }
        cp_commit();
        cp_wait_all();
        __syncthreads();
    }

    // Gram pair tables
    const int GJ[6] = {0,0,0,1,1,2}, GL[6] = {1,2,3,2,3,3};
    const int HJ[10] = {0,0,0,0,1,1,1,2,2,3}, HL[10] = {0,1,2,3,1,2,3,2,3,3};

    for (int chunk = 0; chunk < NCH; ++chunk) {
        const int cur = chunk & 1;
        const int t0  = chunk * CSTEPS;

        // prefetch next chunk
        if (chunk + 1 < NCH) {
            const int nb = cur ^ 1;
            const size_t nt = (size_t)(t0 + CSTEPS) * DK;
            #pragma unroll
            for (int u = 0; u < 4; ++u) {
                int id = u * 128 + tid;
                int t = id >> 5, c = id & 31;
                cp16(su32(&kq[nb][0][t][perm(c) * 4]), gk + nt + t * DK + c * 4);
                cp16(su32(&kq[nb][1][t][perm(c) * 4]), gq + nt + t * DK + c * 4);
            }
            {
                int i = tid >> 3, j = tid & 7;
                cp4(su32(&vT[nb][j][i]), gv + nt + (size_t)i * DK + vbase + j);
            }
        }
        cp_commit();

        // ---- Gram: warp ss computes its super-step's 6 G + 10 H dots ----
        {
            const int s = w * 4;
            float res[16];
            #pragma unroll
            for (int d = 0; d < 16; ++d) {
                int jj = (d < 6) ? GJ[d] : HJ[d - 6];
                int ll = (d < 6) ? GL[d] : HL[d - 6];
                const float4 av = *(const float4*)&kq[cur][0][s + jj][lane * 4];
                const float4 bv = (d < 6)
                    ? *(const float4*)&kq[cur][0][s + ll][lane * 4]
                    : *(const float4*)&kq[cur][1][s + ll][lane * 4];
                res[d] = av.x * bv.x + av.y * bv.y + av.z * bv.z + av.w * bv.w;
            }
            #pragma unroll
            for (int off = 16; off; off >>= 1) {
                #pragma unroll
                for (int d = 0; d < 16; ++d)
                    res[d] += __shfl_xor_sync(0xffffffffu, res[d], off);
            }
            if (lane == 0) {
                #pragma unroll
                for (int d = 0; d < 6; ++d)  Gm[w][GJ[d]][GL[d]] = res[d];
                #pragma unroll
                for (int d = 0; d < 10; ++d) Hm[w][HJ[d]][HL[d]] = res[d + 6];
            }
        }

        // stage this thread's v row into registers
        float vreg[CSTEPS];
        #pragma unroll
        for (int jj = 0; jj < 4; ++jj)
            *(float4*)&vreg[jj * 4] = *(const float4*)&vT[cur][row][jj * 4];

        __syncthreads();   // Gm/Hm visible

        // ---- 4 super-steps ----
        #pragma unroll
        for (int ss = 0; ss < 4; ++ss) {
            const int s = ss * 4;

            ull kr[4][4];
            float wk[4], mk[4], wq[4], mq[4];
            #pragma unroll
            for (int l = 0; l < 4; ++l) {
                const float4 ka = *(const float4*)&kq[cur][0][s + l][g * 4];
                const float4 kb = *(const float4*)&kq[cur][0][s + l][64 + g * 4];
                const float4 qa = *(const float4*)&kq[cur][1][s + l][g * 4];
                const float4 qb = *(const float4*)&kq[cur][1][s + l][64 + g * 4];
                kr[l][0] = pk(ka.x, ka.y); kr[l][1] = pk(ka.z, ka.w);
                kr[l][2] = pk(kb.x, kb.y); kr[l][3] = pk(kb.z, kb.w);
                const ull q0 = pk(qa.x, qa.y), q1 = pk(qa.z, qa.w);
                const ull q2 = pk(qb.x, qb.y), q3 = pk(qb.z, qb.w);

                wk[l] = hadd2(add2(fma2(W0, kr[l][0], mul2(W1, kr[l][1])),
                                   fma2(W2, kr[l][2], mul2(W3, kr[l][3]))));
                if (l > 0)
                    mk[l] = hadd2(add2(fma2(M0, kr[l][0], mul2(M1, kr[l][1])),
                                       fma2(M2, kr[l][2], mul2(M3, kr[l][3]))));
                wq[l] = hadd2(add2(fma2(W0, q0, mul2(W1, q1)),
                                   fma2(W2, q2, mul2(W3, q3))));
                mq[l] = hadd2(add2(fma2(M0, q0, mul2(M1, q1)),
                                   fma2(M2, q2, mul2(M3, q3))));
            }
            mk[0] = 0.0f;

            // one interleaved butterfly: 15 reductions over 16-lane halves
            #pragma unroll
            for (int off = 8; off; off >>= 1) {
                wk[0] += __shfl_xor_sync(0xffffffffu, wk[0], off);
                wk[1] += __shfl_xor_sync(0xffffffffu, wk[1], off);
                wk[2] += __shfl_xor_sync(0xffffffffu, wk[2], off);
                wk[3] += __shfl_xor_sync(0xffffffffu, wk[3], off);
                mk[1] += __shfl_xor_sync(0xffffffffu, mk[1], off);
                mk[2] += __shfl_xor_sync(0xffffffffu, mk[2], off);
                mk[3] += __shfl_xor_sync(0xffffffffu, mk[3], off);
                wq[0] += __shfl_xor_sync(0xffffffffu, wq[0], off);
                wq[1] += __shfl_xor_sync(0xffffffffu, wq[1], off);
                wq[2] += __shfl_xor_sync(0xffffffffu, wq[2], off);
                wq[3] += __shfl_xor_sync(0xffffffffu, wq[3], off);
                mq[0] += __shfl_xor_sync(0xffffffffu, mq[0], off);
                mq[1] += __shfl_xor_sync(0xffffffffu, mq[1], off);
                mq[2] += __shfl_xor_sync(0xffffffffu, mq[2], off);
                mq[3] += __shfl_xor_sync(0xffffffffu, mq[3], off);
            }

            // scalar 4-step recurrence (uniform within each 16-lane half)
            float rr[4];
            #pragma unroll
            for (int j = 0; j < 4; ++j) {
                const int i = s + j;
                const float r = fmaf(cCP[i], wk[j], -vreg[i]);
                rr[j] = r;
                const float ta = cA[i] * r;
                const float tb = cB[i] * r;
                const float yv = cCY[i] *
                    (wq[j] + cS[i] * mq[j] + ta * Hm[ss][j][j]);
                if (g == 0) yb[cur][i][row] = yv;
                #pragma unroll
                for (int l = j + 1; l < 4; ++l) {
                    const float Gjl = Gm[ss][j][l];
                    const float Hjl = Hm[ss][j][l];
                    wk[l] = fmaf(cS[i], mk[l], wk[l]); wk[l] = fmaf(ta, Gjl, wk[l]);
                    mk[l] = fmaf(tb, Gjl, mk[l]);
                    wq[l] = fmaf(cS[i], mq[l], wq[l]); wq[l] = fmaf(ta, Hjl, wq[l]);
                    mq[l] = fmaf(tb, Hjl, mq[l]);
                }
            }

            // rank-4 closed-form state update (W uses pre-update m)
            {
                const ull Pv = pk(cP4[ss], cP4[ss]);
                W0 = fma2(Pv, M0, W0); W1 = fma2(Pv, M1, W1);
                W2 = fma2(Pv, M2, W2); W3 = fma2(Pv, M3, W3);
                #pragma unroll
                for (int j = 0; j < 4; ++j) {
                    const float zw = cZW4[s + j] * rr[j];
                    const float zm = cB[s + j] * rr[j];
                    const ull zw2 = pk(zw, zw), zm2 = pk(zm, zm);
                    W0 = fma2(zw2, kr[j][0], W0); W1 = fma2(zw2, kr[j][1], W1);
                    W2 = fma2(zw2, kr[j][2], W2); W3 = fma2(zw2, kr[j][3], W3);
                    M0 = fma2(zm2, kr[j][0], M0); M1 = fma2(zm2, kr[j][1], M1);
                    M2 = fma2(zm2, kr[j][2], M2); M3 = fma2(zm2, kr[j][3], M3);
                }
            }
        }

        // chunk-end rescale to fresh frame
        {
            const ull c16 = pk(C16F, C16F);
            const ull b16 = pk(B16F, B16F);
            W0 = mul2(c16, W0); W1 = mul2(c16, W1);
            W2 = mul2(c16, W2); W3 = mul2(c16, W3);
            M0 = mul2(b16, M0); M1 = mul2(b16, M1);
            M2 = mul2(b16, M2); M3 = mul2(b16, M3);
        }

        cp_wait_all();
        __syncthreads();

        // writeback this chunk's y
        {
            int i = tid >> 3, j = tid & 7;
            gy[(size_t)(t0 + i) * DK + vbase + j] = yb[cur][i][j];
        }
    }
}

extern "C" void kernel_launch(void* const* d_in, const int* in_sizes, int n_in,
                              void* d_out, int out_size) {
    const float* Q = (const float*)d_in[0];
    const float* K = (const float*)d_in[1];
    const float* V = (const float*)d_in[2];
    float* Y = (float*)d_out;
    (void)in_sizes; (void)n_in; (void)out_size;
    titans_kernel<<<256, 128>>>(Q, K, V, Y);
}

// round 10
// speedup vs baseline: 1.0984x; 1.0984x over previous
#include <cuda_runtime.h>
#include <cstdint>

// TitansMemory B=16 L=8192 DK=DV=128 — direct recurrence v5.
// 1 row per warp (2048 warps, 16/SM), rescaled-state math (R8, validated).
// Per step: 3 dots from pre-update state (Wk, Wq, mq) reduced in ONE folded
// multi-value butterfly (8 shfl total); kq precomputed once per chunk.
//   r = CP_i*(W.k) - v ; W += S_i*m + A_i*r*k ; m += B_i*r*k
//   y = CY_i*(W.q + S_i*(m.q) + A_i*r*(k.q))   [all pre-update dots]
// 128 CTAs x 512 thr; k/q/v double-buffered via cp.async.

#define CSTEPS 16
#define L_SEQ  8192
#define NCH    (L_SEQ / CSTEPS)
#define DK     128

using ull = unsigned long long;

__device__ __forceinline__ ull pk(float lo, float hi) {
    ull r; asm("mov.b64 %0,{%1,%2};" : "=l"(r) : "f"(lo), "f"(hi)); return r;
}
__device__ __forceinline__ float hadd2(ull p) {
    float lo, hi; asm("mov.b64 {%0,%1},%2;" : "=f"(lo), "=f"(hi) : "l"(p));
    return lo + hi;
}
__device__ __forceinline__ ull mul2(ull a, ull b) {
    ull d; asm("mul.rn.f32x2 %0,%1,%2;" : "=l"(d) : "l"(a), "l"(b)); return d;
}
__device__ __forceinline__ ull fma2(ull a, ull b, ull c) {
    ull d; asm("fma.rn.f32x2 %0,%1,%2,%3;" : "=l"(d) : "l"(a), "l"(b), "l"(c)); return d;
}
__device__ __forceinline__ unsigned su32(const void* p) {
    return (unsigned)__cvta_generic_to_shared(p);
}
__device__ __forceinline__ void cp16(unsigned s, const void* g) {
    asm volatile("cp.async.cg.shared.global [%0],[%1],16;" :: "r"(s), "l"(g));
}
__device__ __forceinline__ void cp4(unsigned s, const void* g) {
    asm volatile("cp.async.ca.shared.global [%0],[%1],4;" :: "r"(s), "l"(g));
}
__device__ __forceinline__ void cp_commit() {
    asm volatile("cp.async.commit_group;" ::: "memory");
}
__device__ __forceinline__ void cp_wait_all() {
    asm volatile("cp.async.wait_group 0;" ::: "memory");
}

__global__ __launch_bounds__(512, 1)
void titans_kernel(const float* __restrict__ Q,
                   const float* __restrict__ K,
                   const float* __restrict__ V,
                   float* __restrict__ Y) {
    static constexpr float cCP[16] = {  // 0.98^i
        1.0f, 0.98f, 0.9604f, 0.941192f, 0.92236816f, 0.9039207968f,
        0.8858423809f, 0.8681255332f, 0.8507630226f, 0.8337477621f,
        0.8170728069f, 0.8007313508f, 0.7847167237f, 0.7690223892f,
        0.7536419414f, 0.7385691035f };
    static constexpr float cCY[16] = {  // 0.98^(i+1)
        0.98f, 0.9604f, 0.941192f, 0.92236816f, 0.9039207968f, 0.8858423809f,
        0.8681255332f, 0.8507630226f, 0.8337477621f, 0.8170728069f,
        0.8007313508f, 0.7847167237f, 0.7690223892f, 0.7536419414f,
        0.7385691035f, 0.7237977214f };
    static constexpr float cS[16] = {   // -0.1*(0.9/0.98)^(i+1)
        -0.09183673469f, -0.08433985839f, -0.07745414463f, -0.07113064017f,
        -0.06532344097f, -0.05999029968f, -0.05509252418f, -0.05059456302f,
        -0.04646378542f, -0.04267021926f, -0.03918632342f, -0.03598663375f,
        -0.03304811221f, -0.03034970510f, -0.02787207213f, -0.02559670445f };
    static constexpr float cA[16] = {   // -0.02/0.98^(i+1)
        -0.02040816327f, -0.02082465640f, -0.02124964939f, -0.02168331570f,
        -0.02212583235f, -0.02257738015f, -0.02303814301f, -0.02350830920f,
        -0.02398807061f, -0.02447762307f, -0.02497716640f, -0.02548690449f,
        -0.02600704540f, -0.02653780143f, -0.02707938921f, -0.02763202981f };
    static constexpr float cB[16] = {   // 0.2/0.9^(i+1)
        0.2222222222f, 0.2469135802f, 0.2743484225f, 0.3048315805f,
        0.3387017561f, 0.3763352846f, 0.4181503162f, 0.4646114624f,
        0.5162349582f, 0.5735943980f, 0.6373271089f, 0.7081412321f,
        0.7868235912f, 0.8742484347f, 0.9713871497f, 1.0793190552f };
    constexpr float C16F = 0.7237977214f;   // 0.98^16
    constexpr float B16F = 0.1853020189f;   // 0.9^16

    __shared__ float kb[2][CSTEPS][DK];
    __shared__ float qb[2][CSTEPS][DK];
    __shared__ float vT[2][16][20];          // [row][step]
    __shared__ float skq[2][CSTEPS];         // k_t.q_t (per chunk)
    __shared__ float yb[2][CSTEPS][16];      // [step][row]

    const int tid  = threadIdx.x;
    const int w    = tid >> 5;               // warp = row 0..15
    const int lane = tid & 31;

    const int b     = blockIdx.x >> 3;       // 16 batches
    const int vbase = (blockIdx.x & 7) << 4; // 8 groups x 16 rows

    const size_t base = (size_t)b * L_SEQ * DK;
    const float* gk = K + base;
    const float* gq = Q + base;
    const float* gv = V + base;
    float*       gy = Y + base;

    // state: lane owns What[w, 4*lane..+3], mhat same (2 f32x2 pairs each)
    ull W01 = 0, W23 = 0, M01 = 0, M23 = 0;

    // ---- preload chunk 0 ----
    {
        cp16(su32(&kb[0][0][0]) + tid * 16, gk + tid * 4);
        cp16(su32(&qb[0][0][0]) + tid * 16, gq + tid * 4);
        if (tid < 256) {
            int i = tid >> 4, j = tid & 15;
            cp4(su32(&vT[0][j][i]), gv + (size_t)i * DK + vbase + j);
        }
        cp_commit();
        cp_wait_all();
        __syncthreads();
    }

    for (int chunk = 0; chunk < NCH; ++chunk) {
        const int cur = chunk & 1;
        const int t0  = chunk * CSTEPS;

        // ---- per-chunk kq precompute: warp w handles step w ----
        {
            const float4 k4 = *(const float4*)&kb[cur][w][lane << 2];
            const float4 q4 = *(const float4*)&qb[cur][w][lane << 2];
            float p = k4.x * q4.x + k4.y * q4.y + k4.z * q4.z + k4.w * q4.w;
            #pragma unroll
            for (int off = 16; off; off >>= 1)
                p += __shfl_xor_sync(0xffffffffu, p, off);
            if (lane == 0) skq[cur][w] = p;
        }

        // stage this warp's v row (broadcast LDS.128)
        float vreg[CSTEPS];
        #pragma unroll
        for (int jj = 0; jj < 4; ++jj)
            *(float4*)&vreg[jj * 4] = *(const float4*)&vT[cur][w][jj * 4];

        // prefetch next chunk into other buffer
        if (chunk + 1 < NCH) {
            const int nb = cur ^ 1;
            const size_t nt = (size_t)(t0 + CSTEPS) * DK;
            cp16(su32(&kb[nb][0][0]) + tid * 16, gk + nt + tid * 4);
            cp16(su32(&qb[nb][0][0]) + tid * 16, gq + nt + tid * 4);
            if (tid < 256) {
                int i = tid >> 4, j = tid & 15;
                cp4(su32(&vT[nb][j][i]), gv + nt + (size_t)i * DK + vbase + j);
            }
        }
        cp_commit();

        __syncthreads();   // skq visible

        // stage kq values (broadcast)
        float kqreg[CSTEPS];
        #pragma unroll
        for (int jj = 0; jj < 4; ++jj)
            *(float4*)&kqreg[jj * 4] = *(const float4*)&skq[cur][jj * 4];

        const bool amp1 = (lane & 1);
        const bool amp2 = (lane & 2);
        const int  base0 = lane & 28;     // class-0 lane in this 4-group

        // ---- 16 sequential steps ----
        #pragma unroll
        for (int i = 0; i < CSTEPS; ++i) {
            const float4 k4 = *(const float4*)&kb[cur][i][lane << 2];
            const float4 q4 = *(const float4*)&qb[cur][i][lane << 2];
            const ull k01 = pk(k4.x, k4.y), k23 = pk(k4.z, k4.w);
            const ull q01 = pk(q4.x, q4.y), q23 = pk(q4.z, q4.w);

            // three dots on pre-update state (per-lane partials)
            float wk = hadd2(fma2(W01, k01, mul2(W23, k23)));
            float wq = hadd2(fma2(W01, q01, mul2(W23, q23)));
            float mq = hadd2(fma2(M01, q01, mul2(M23, q23)));

            // folded butterfly:
            // phase1 (xor1): merge (wk,wq) -> a (even lanes wk, odd wq)
            float send1 = amp1 ? wk : wq;
            float recv1 = __shfl_xor_sync(0xffffffffu, send1, 1);
            float a = (amp1 ? wq : wk) + recv1;
            // phase2 (xor2): merge a with mq -> c
            // class (lane&3): 0 = wk, 1 = wq, 2 = mq-even, 3 = mq-odd
            float send2 = amp2 ? a : mq;
            float recv2 = __shfl_xor_sync(0xffffffffu, send2, 2);
            float c = (amp2 ? mq : a) + recv2;
            // phase3: classic butterfly over the eight 4-lane groups
            c += __shfl_xor_sync(0xffffffffu, c, 4);
            c += __shfl_xor_sync(0xffffffffu, c, 8);
            c += __shfl_xor_sync(0xffffffffu, c, 16);
            // broadcast wk (class 0) to all lanes
            const float wkall = __shfl_sync(0xffffffffu, c, base0);

            const float r  = fmaf(cCP[i], wkall, -vreg[i]);
            const float ta = cA[i] * r;
            const float tb = cB[i] * r;
            const ull a2 = pk(ta, ta);
            const ull b2 = pk(tb, tb);
            const ull s2 = pk(cS[i], cS[i]);

            // y: class-2 lane has mq-even; fetch mq-odd (xor1) and wq (xor3)
            const float mqo = __shfl_xor_sync(0xffffffffu, c, 1);
            const float wqv = __shfl_xor_sync(0xffffffffu, c, 3);
            if (lane == 2)
                yb[cur][i][w] = cCY[i] *
                    (wqv + cS[i] * (c + mqo) + ta * kqreg[i]);

            // W += s*m + a*k ; m += b*k   (pre-update m used for W)
            W01 = fma2(s2, M01, W01); W01 = fma2(a2, k01, W01);
            M01 = fma2(b2, k01, M01);
            W23 = fma2(s2, M23, W23); W23 = fma2(a2, k23, W23);
            M23 = fma2(b2, k23, M23);
        }

        // chunk-end rescale
        {
            const ull c16 = pk(C16F, C16F);
            const ull b16 = pk(B16F, B16F);
            W01 = mul2(c16, W01); W23 = mul2(c16, W23);
            M01 = mul2(b16, M01); M23 = mul2(b16, M23);
        }

        cp_wait_all();
        __syncthreads();

        // writeback this chunk's y
        if (tid < 256) {
            int i = tid >> 4, j = tid & 15;
            gy[(size_t)(t0 + i) * DK + vbase + j] = yb[cur][i][j];
        }
    }
}

extern "C" void kernel_launch(void* const* d_in, const int* in_sizes, int n_in,
                              void* d_out, int out_size) {
    const float* Q = (const float*)d_in[0];
    const float* K = (const float*)d_in[1];
    const float* V = (const float*)d_in[2];
    float* Y = (float*)d_out;
    (void)in_sizes; (void)n_in; (void)out_size;
    titans_kernel<<<128, 512>>>(Q, K, V, Y);
}